// round 5
// baseline (speedup 1.0000x reference)
#include <cuda_runtime.h>

#define NX    20      // x in [0, 20)
#define KSER  64      // fp32 series terms used in setup
#define DEG   12      // polynomial degree of log(2F1) fit
#define NC    (DEG+1) // 13 coefficients / nodes
#define NPAIR 7       // ceil(14/2) float2 coefficient pairs (c13 = 0 pad)
// fit interval z in [0, 0.75]:  t = z*8/3 - 1
#define ZC    0.375f
#define ZH    0.375f
#define TSCALE 2.6666667f

// Device tables (rewritten by setup each launch; deterministic).
__device__ float2 g_P2[NPAIR][NX];  // (c_{2j}, c_{2j+1}) of log(2F1) monomial fit, +G folded in c0
__device__ float  g_sc[4];          // 0:r 1:alpha 2:r*log_alpha 3:c0=log(b)-log(a+b)

// ---- fp32 setup: grid = NX blocks, 64 threads ----
__global__ void setup_kernel(const float* log_r, const float* log_alpha,
                             const float* log_a, const float* log_b) {
    const float PI = 3.14159265358979323846f;
    int x = blockIdx.x;
    int i = threadIdx.x;

    float r  = __expf(log_r[0]);
    float a  = __expf(log_a[0]);
    float b  = __expf(log_b[0]);
    float xf = (float)x;
    float p = r + xf, q = a, s = a + b + xf;

    __shared__ float inv[KSER];
    __shared__ float C[KSER];
    __shared__ float f[NC];
    __shared__ float gsh;

    if (i < KSER)
        inv[i] = __frcp_rn((s + (float)i) * ((float)i + 1.0f));
    __syncthreads();

    if (i < KSER) {
        float prod = 1.0f;
        for (int j = 0; j < i; j++)
            prod *= (p + (float)j) * (q + (float)j) * inv[j];
        C[i] = prod;
    }
    __syncthreads();

    if (i < NC) {
        float t = cosf(PI * ((float)i + 0.5f) / (float)NC);
        float z = ZC + ZH * t;
        float acc = C[KSER - 1];
        for (int m = KSER - 2; m >= 0; m--)
            acc = __fmaf_rn(acc, z, C[m]);
        f[i] = logf(acc);
    }
    if (i == 32) {
        gsh = lgammaf(r + xf) - lgammaf(r) - lgammaf(xf + 1.0f)
            + logf(a) + lgammaf(a + b) - lgammaf(a)
            - lgammaf(a + b + xf) + lgammaf(a + xf);
    }
    if (i == 33 && x == 0) {
        g_sc[0] = r;
        g_sc[1] = __expf(log_alpha[0]);
        g_sc[2] = r * log_alpha[0];
        g_sc[3] = logf(b) - logf(a + b);
    }
    __syncthreads();

    // DCT + Chebyshev->monomial conversion (warp 0, shuffle-based)
    if (i < 32) {
        float ci = 0.0f;
        if (i < NC) {
            for (int k = 0; k < NC; k++)
                ci += f[k] * cosf(PI * (float)i * ((float)k + 0.5f) / (float)NC);
            ci *= (i == 0) ? (1.0f / NC) : (2.0f / NC);
        }
        float Tp = (i == 0) ? 1.0f : 0.0f;
        float Tc = (i == 1) ? 1.0f : 0.0f;
        float c0v = __shfl_sync(0xffffffffu, ci, 0);
        float c1v = __shfl_sync(0xffffffffu, ci, 1);
        float mono = c0v * Tp + c1v * Tc;
        for (int j = 2; j <= DEG; j++) {
            float cj = __shfl_sync(0xffffffffu, ci, j);
            float sh = __shfl_up_sync(0xffffffffu, Tc, 1);
            if (i == 0) sh = 0.0f;
            float Tn = 2.0f * sh - Tp;
            mono = __fmaf_rn(cj, Tn, mono);
            Tp = Tc; Tc = Tn;
        }
        // packed store: pair j = i>>1, component i&1
        if (i < NC) {
            float v = mono + ((i == 0) ? gsh : 0.0f);
            ((float*)g_P2)[((i >> 1) * NX + x) * 2 + (i & 1)] = v;
        }
        if (i == NC)   // zero pad c13
            ((float*)g_P2)[((NC >> 1) * NX + x) * 2 + 1] = 0.0f;
    }
}

// ---- Main kernel ----
__device__ __forceinline__ float eval_elem(int x, float t_x, float T,
                                           float r, float alpha,
                                           float r_la, float c0,
                                           const float2* sC) {
    float aT = T + alpha;
    float lT = __logf(aT);
    float dt = T - t_x;
    float z  = dt * __frcp_rn(aT);
    float t  = __fmaf_rn(z, TSCALE, -1.0f);
    float u  = t * t;
    int xc = min(x, NX - 1);
    const float2* col = sC + xc;                  // stride NX over pair index
    float2 p6 = col[6 * NX];
    float ae = p6.x, ao = p6.y;                   // even / odd Horner chains
#pragma unroll
    for (int j = 5; j >= 0; j--) {
        float2 pj = col[j * NX];
        ae = __fmaf_rn(ae, u, pj.x);
        ao = __fmaf_rn(ao, u, pj.y);
    }
    float sacc = __fmaf_rn(ao, t, ae);            // log 2F1 (+ lgamma combo)
    float common = __fmaf_rn(-r, lT, r_la);
    float lz = __logf(z);
    float ll1 = __fmaf_rn(__int2float_rn(x), lz, common + sacc);
    float ll0 = common + c0;
    return (x == 0) ? ll0 : ll1;
}

__global__ __launch_bounds__(256, 8) void bgnbd_kernel(
    const int4* __restrict__ xin,
    const float4* __restrict__ txin,
    const float4* __restrict__ Tin,
    float4* __restrict__ out,
    int n)
{
    __shared__ float2 sC[NPAIR][NX];
    int tid = threadIdx.x;
    for (int i = tid; i < NPAIR * NX; i += blockDim.x)
        ((float2*)sC)[i] = ((const float2*)g_P2)[i];
    float r = g_sc[0], alpha = g_sc[1], r_la = g_sc[2], c0 = g_sc[3];
    __syncthreads();

    int i = blockIdx.x * blockDim.x + tid;
    int base_e = i * 4;
    if (base_e >= n) return;

    if (base_e + 3 < n) {
        int4   xv = xin[i];
        float4 tv = txin[i];
        float4 Tv = Tin[i];
        float4 o;
        o.x = eval_elem(xv.x, tv.x, Tv.x, r, alpha, r_la, c0, &sC[0][0]);
        o.y = eval_elem(xv.y, tv.y, Tv.y, r, alpha, r_la, c0, &sC[0][0]);
        o.z = eval_elem(xv.z, tv.z, Tv.z, r, alpha, r_la, c0, &sC[0][0]);
        o.w = eval_elem(xv.w, tv.w, Tv.w, r, alpha, r_la, c0, &sC[0][0]);
        out[i] = o;
    } else {
        const int*   xsc = (const int*)xin;
        const float* tsc = (const float*)txin;
        const float* Tsc = (const float*)Tin;
        float*       osc = (float*)out;
        for (int e = base_e; e < n; e++)
            osc[e] = eval_elem(xsc[e], tsc[e], Tsc[e], r, alpha, r_la, c0, &sC[0][0]);
    }
}

extern "C" void kernel_launch(void* const* d_in, const int* in_sizes, int n_in,
                              void* d_out, int out_size) {
    const int*   x   = (const int*)d_in[0];
    const float* t_x = (const float*)d_in[1];
    const float* T   = (const float*)d_in[2];
    const float* lr  = (const float*)d_in[3];
    const float* lal = (const float*)d_in[4];
    const float* la  = (const float*)d_in[5];
    const float* lb  = (const float*)d_in[6];
    float* out = (float*)d_out;
    int n = in_sizes[0];

    setup_kernel<<<NX, 64>>>(lr, lal, la, lb);

    int n4 = (n + 3) / 4;
    int threads = 256;
    int blocks = (n4 + threads - 1) / threads;
    bgnbd_kernel<<<blocks, threads>>>((const int4*)x, (const float4*)t_x,
                                      (const float4*)T, (float4*)out, n);
}

// round 6
// speedup vs baseline: 1.2806x; 1.2806x over previous
#include <cuda_runtime.h>

#define NX    20      // x in [0, 20)
#define KSER  64      // fp32 series terms used in setup
#define DEG   9       // polynomial degree of log(2F1) fit
#define NC    (DEG+1) // 10 coefficients / nodes
// fit interval z in [0, 0.75]:  t = z*8/3 - 1
#define ZC    0.375f
#define ZH    0.375f
#define TSCALE 2.6666667f

// Device tables (rewritten by setup each launch; deterministic).
__device__ float g_P[NC][NX];   // monomial coeffs of log(2F1) in t (+lgamma combo in k=0), [k][x]
__device__ float g_sc[4];       // 0:r 1:alpha 2:r*log_alpha 3:c0=log(b)-log(a+b)

// ---- fp32 setup: grid = NX blocks, 64 threads ----
__global__ void setup_kernel(const float* log_r, const float* log_alpha,
                             const float* log_a, const float* log_b) {
    const float PI = 3.14159265358979323846f;
    int x = blockIdx.x;
    int i = threadIdx.x;

    float r  = __expf(log_r[0]);
    float a  = __expf(log_a[0]);
    float b  = __expf(log_b[0]);
    float xf = (float)x;
    float p = r + xf, q = a, s = a + b + xf;

    __shared__ float inv[KSER];
    __shared__ float C[KSER];
    __shared__ float f[NC];
    __shared__ float gsh;

    if (i < KSER)
        inv[i] = __frcp_rn((s + (float)i) * ((float)i + 1.0f));
    __syncthreads();

    if (i < KSER) {
        float prod = 1.0f;
        for (int j = 0; j < i; j++)
            prod *= (p + (float)j) * (q + (float)j) * inv[j];
        C[i] = prod;
    }
    __syncthreads();

    if (i < NC) {
        float t = cosf(PI * ((float)i + 0.5f) / (float)NC);
        float z = ZC + ZH * t;
        float acc = C[KSER - 1];
        for (int m = KSER - 2; m >= 0; m--)
            acc = __fmaf_rn(acc, z, C[m]);
        f[i] = logf(acc);
    }
    if (i == 32) {
        gsh = lgammaf(r + xf) - lgammaf(r) - lgammaf(xf + 1.0f)
            + logf(a) + lgammaf(a + b) - lgammaf(a)
            - lgammaf(a + b + xf) + lgammaf(a + xf);
    }
    if (i == 33 && x == 0) {
        g_sc[0] = r;
        g_sc[1] = __expf(log_alpha[0]);
        g_sc[2] = r * log_alpha[0];
        g_sc[3] = logf(b) - logf(a + b);
    }
    __syncthreads();

    // DCT + Chebyshev->monomial conversion (warp 0, shuffle-based)
    if (i < 32) {
        float ci = 0.0f;
        if (i < NC) {
            for (int k = 0; k < NC; k++)
                ci += f[k] * cosf(PI * (float)i * ((float)k + 0.5f) / (float)NC);
            ci *= (i == 0) ? (1.0f / NC) : (2.0f / NC);
        }
        float Tp = (i == 0) ? 1.0f : 0.0f;
        float Tc = (i == 1) ? 1.0f : 0.0f;
        float c0v = __shfl_sync(0xffffffffu, ci, 0);
        float c1v = __shfl_sync(0xffffffffu, ci, 1);
        float mono = c0v * Tp + c1v * Tc;
        for (int j = 2; j <= DEG; j++) {
            float cj = __shfl_sync(0xffffffffu, ci, j);
            float sh = __shfl_up_sync(0xffffffffu, Tc, 1);
            if (i == 0) sh = 0.0f;
            float Tn = 2.0f * sh - Tp;
            mono = __fmaf_rn(cj, Tn, mono);
            Tp = Tc; Tc = Tn;
        }
        if (i < NC)
            g_P[i][x] = mono + ((i == 0) ? gsh : 0.0f);
    }
}

// ---- Main kernel ----
__device__ __forceinline__ float eval_elem(int x, float t_x, float T,
                                           float r, float alpha,
                                           float r_la, float c0,
                                           const float* sP) {
    float aT = T + alpha;
    float lT = __logf(aT);
    float dt = T - t_x;
    float z  = dt * __frcp_rn(aT);
    float lz = __logf(z);
    float t  = __fmaf_rn(z, TSCALE, -1.0f);
    int xc = min(x, NX - 1);
    const float* col = sP + xc;               // stride NX over k; conflict-free banks
    float sacc = col[DEG * NX];
#pragma unroll
    for (int k = DEG - 1; k >= 0; k--)
        sacc = __fmaf_rn(sacc, t, col[k * NX]);
    float common = __fmaf_rn(-r, lT, r_la);
    float ll1 = __fmaf_rn(__int2float_rn(x), lz, common + sacc);
    float ll0 = common + c0;
    return (x == 0) ? ll0 : ll1;
}

__global__ __launch_bounds__(256) void bgnbd_kernel(
    const int4* __restrict__ xin,
    const float4* __restrict__ txin,
    const float4* __restrict__ Tin,
    float4* __restrict__ out,
    int n)
{
    __shared__ float sP[NC][NX];
    int tid = threadIdx.x;
    for (int i = tid; i < NC * NX; i += blockDim.x)
        ((float*)sP)[i] = ((const float*)g_P)[i];
    float r = g_sc[0], alpha = g_sc[1], r_la = g_sc[2], c0 = g_sc[3];
    __syncthreads();

    int i = blockIdx.x * blockDim.x + tid;    // 8-element group index
    int base_e = i * 8;
    if (base_e >= n) return;

    if (base_e + 7 < n) {
        int v0 = i * 2, v1 = v0 + 1;
        // front-batched loads: 6 independent LDG.128 (MLP_p1 = 6)
        int4   xa = xin[v0];
        int4   xb = xin[v1];
        float4 ta = txin[v0];
        float4 tb = txin[v1];
        float4 Ta = Tin[v0];
        float4 Tb = Tin[v1];
        float4 oa, ob;
        oa.x = eval_elem(xa.x, ta.x, Ta.x, r, alpha, r_la, c0, &sP[0][0]);
        oa.y = eval_elem(xa.y, ta.y, Ta.y, r, alpha, r_la, c0, &sP[0][0]);
        oa.z = eval_elem(xa.z, ta.z, Ta.z, r, alpha, r_la, c0, &sP[0][0]);
        oa.w = eval_elem(xa.w, ta.w, Ta.w, r, alpha, r_la, c0, &sP[0][0]);
        ob.x = eval_elem(xb.x, tb.x, Tb.x, r, alpha, r_la, c0, &sP[0][0]);
        ob.y = eval_elem(xb.y, tb.y, Tb.y, r, alpha, r_la, c0, &sP[0][0]);
        ob.z = eval_elem(xb.z, tb.z, Tb.z, r, alpha, r_la, c0, &sP[0][0]);
        ob.w = eval_elem(xb.w, tb.w, Tb.w, r, alpha, r_la, c0, &sP[0][0]);
        out[v0] = oa;
        out[v1] = ob;
    } else {
        const int*   xsc = (const int*)xin;
        const float* tsc = (const float*)txin;
        const float* Tsc = (const float*)Tin;
        float*       osc = (float*)out;
        for (int e = base_e; e < n; e++)
            osc[e] = eval_elem(xsc[e], tsc[e], Tsc[e], r, alpha, r_la, c0, &sP[0][0]);
    }
}

extern "C" void kernel_launch(void* const* d_in, const int* in_sizes, int n_in,
                              void* d_out, int out_size) {
    const int*   x   = (const int*)d_in[0];
    const float* t_x = (const float*)d_in[1];
    const float* T   = (const float*)d_in[2];
    const float* lr  = (const float*)d_in[3];
    const float* lal = (const float*)d_in[4];
    const float* la  = (const float*)d_in[5];
    const float* lb  = (const float*)d_in[6];
    float* out = (float*)d_out;
    int n = in_sizes[0];

    setup_kernel<<<NX, 64>>>(lr, lal, la, lb);

    int n8 = (n + 7) / 8;
    int threads = 256;
    int blocks = (n8 + threads - 1) / threads;
    bgnbd_kernel<<<blocks, threads>>>((const int4*)x, (const float4*)t_x,
                                      (const float4*)T, (float4*)out, n);
}

// round 7
// speedup vs baseline: 1.2910x; 1.0082x over previous
#include <cuda_runtime.h>

#define NX    20      // x in [0, 20)
#define KSER  64      // fp32 series terms used in setup
#define DEG   9       // polynomial degree of log(2F1) fit
#define NC    (DEG+1) // 10 coefficients / nodes
// fit interval z in [0, 0.75]:  t = z*8/3 - 1
#define ZC    0.375f
#define ZH    0.375f
#define TSCALE 2.6666667f

// Device tables (rewritten by setup each launch; deterministic).
__device__ float g_P[NC][NX];   // monomial coeffs of log(2F1) in t (+lgamma combo in k=0), [k][x]
__device__ float g_sc[4];       // 0:r 1:alpha 2:r*log_alpha 3:c0=log(b)-log(a+b)

// ---- fp32 setup: grid = NX blocks, 64 threads ----
__global__ void setup_kernel(const float* log_r, const float* log_alpha,
                             const float* log_a, const float* log_b) {
    const float PI = 3.14159265358979323846f;
    int x = blockIdx.x;
    int i = threadIdx.x;

    float r  = __expf(log_r[0]);
    float a  = __expf(log_a[0]);
    float b  = __expf(log_b[0]);
    float xf = (float)x;
    float p = r + xf, q = a, s = a + b + xf;

    __shared__ float inv[KSER];
    __shared__ float C[KSER];
    __shared__ float f[NC];
    __shared__ float gsh;

    if (i < KSER)
        inv[i] = __frcp_rn((s + (float)i) * ((float)i + 1.0f));
    __syncthreads();

    if (i < KSER) {
        float prod = 1.0f;
        for (int j = 0; j < i; j++)
            prod *= (p + (float)j) * (q + (float)j) * inv[j];
        C[i] = prod;
    }
    __syncthreads();

    if (i < NC) {
        float t = cosf(PI * ((float)i + 0.5f) / (float)NC);
        float z = ZC + ZH * t;
        float acc = C[KSER - 1];
        for (int m = KSER - 2; m >= 0; m--)
            acc = __fmaf_rn(acc, z, C[m]);
        f[i] = logf(acc);
    }
    if (i == 32) {
        gsh = lgammaf(r + xf) - lgammaf(r) - lgammaf(xf + 1.0f)
            + logf(a) + lgammaf(a + b) - lgammaf(a)
            - lgammaf(a + b + xf) + lgammaf(a + xf);
    }
    if (i == 33 && x == 0) {
        g_sc[0] = r;
        g_sc[1] = __expf(log_alpha[0]);
        g_sc[2] = r * log_alpha[0];
        g_sc[3] = logf(b) - logf(a + b);
    }
    __syncthreads();

    // DCT + Chebyshev->monomial conversion (warp 0, shuffle-based)
    if (i < 32) {
        float ci = 0.0f;
        if (i < NC) {
            for (int k = 0; k < NC; k++)
                ci += f[k] * cosf(PI * (float)i * ((float)k + 0.5f) / (float)NC);
            ci *= (i == 0) ? (1.0f / NC) : (2.0f / NC);
        }
        float Tp = (i == 0) ? 1.0f : 0.0f;
        float Tc = (i == 1) ? 1.0f : 0.0f;
        float c0v = __shfl_sync(0xffffffffu, ci, 0);
        float c1v = __shfl_sync(0xffffffffu, ci, 1);
        float mono = c0v * Tp + c1v * Tc;
        for (int j = 2; j <= DEG; j++) {
            float cj = __shfl_sync(0xffffffffu, ci, j);
            float sh = __shfl_up_sync(0xffffffffu, Tc, 1);
            if (i == 0) sh = 0.0f;
            float Tn = 2.0f * sh - Tp;
            mono = __fmaf_rn(cj, Tn, mono);
            Tp = Tc; Tc = Tn;
        }
        if (i < NC)
            g_P[i][x] = mono + ((i == 0) ? gsh : 0.0f);
    }
}

// ---- Main kernel ----
__device__ __forceinline__ float eval_elem(int x, float t_x, float T,
                                           float r, float alpha,
                                           float r_la, float c0,
                                           const float* sP) {
    float aT = T + alpha;
    float lT = __logf(aT);
    float dt = T - t_x;
    float z  = dt * __frcp_rn(aT);
    float lz = __logf(z);
    float t  = __fmaf_rn(z, TSCALE, -1.0f);
    int xc = min(x, NX - 1);
    const float* col = sP + xc;               // stride NX over k; conflict-free banks
    float sacc = col[DEG * NX];
#pragma unroll
    for (int k = DEG - 1; k >= 0; k--)
        sacc = __fmaf_rn(sacc, t, col[k * NX]);
    float common = __fmaf_rn(-r, lT, r_la);
    float ll1 = __fmaf_rn(__int2float_rn(x), lz, common + sacc);
    float ll0 = common + c0;
    return (x == 0) ? ll0 : ll1;
}

__global__ __launch_bounds__(256) void bgnbd_kernel(
    const int4* __restrict__ xin,
    const float4* __restrict__ txin,
    const float4* __restrict__ Tin,
    float4* __restrict__ out,
    int n)
{
    __shared__ float sP[NC][NX];
    int tid = threadIdx.x;
    for (int i = tid; i < NC * NX; i += blockDim.x)
        ((float*)sP)[i] = ((const float*)g_P)[i];
    float r = g_sc[0], alpha = g_sc[1], r_la = g_sc[2], c0 = g_sc[3];
    __syncthreads();

    int stride  = gridDim.x * blockDim.x;          // in 8-elem groups
    int ngroups = n >> 3;                          // full groups
    int g = blockIdx.x * blockDim.x + tid;

    // Software-pipelined grid-stride loop: prefetch group g+stride while computing g.
    int4 xa, xb; float4 ta, tb, Ta, Tb;
    if (g < ngroups) {
        int v0 = g * 2, v1 = v0 + 1;
        xa = xin[v0];  xb = xin[v1];
        ta = txin[v0]; tb = txin[v1];
        Ta = Tin[v0];  Tb = Tin[v1];
    }
    for (int cur = g; cur < ngroups; cur += stride) {
        int nxt = cur + stride;
        int4 xa2, xb2; float4 ta2, tb2, Ta2, Tb2;
        if (nxt < ngroups) {                       // prefetch next group (6 LDG.128)
            int w0 = nxt * 2, w1 = w0 + 1;
            xa2 = xin[w0];  xb2 = xin[w1];
            ta2 = txin[w0]; tb2 = txin[w1];
            Ta2 = Tin[w0];  Tb2 = Tin[w1];
        }
        float4 oa, ob;
        oa.x = eval_elem(xa.x, ta.x, Ta.x, r, alpha, r_la, c0, &sP[0][0]);
        oa.y = eval_elem(xa.y, ta.y, Ta.y, r, alpha, r_la, c0, &sP[0][0]);
        oa.z = eval_elem(xa.z, ta.z, Ta.z, r, alpha, r_la, c0, &sP[0][0]);
        oa.w = eval_elem(xa.w, ta.w, Ta.w, r, alpha, r_la, c0, &sP[0][0]);
        ob.x = eval_elem(xb.x, tb.x, Tb.x, r, alpha, r_la, c0, &sP[0][0]);
        ob.y = eval_elem(xb.y, tb.y, Tb.y, r, alpha, r_la, c0, &sP[0][0]);
        ob.z = eval_elem(xb.z, tb.z, Tb.z, r, alpha, r_la, c0, &sP[0][0]);
        ob.w = eval_elem(xb.w, tb.w, Tb.w, r, alpha, r_la, c0, &sP[0][0]);
        int v0 = cur * 2;
        out[v0]     = oa;
        out[v0 + 1] = ob;
        xa = xa2; xb = xb2; ta = ta2; tb = tb2; Ta = Ta2; Tb = Tb2;
    }

    // Tail elements (n % 8), handled by one thread.
    if (g == 0) {
        const int*   xsc = (const int*)xin;
        const float* tsc = (const float*)txin;
        const float* Tsc = (const float*)Tin;
        float*       osc = (float*)out;
        for (int e = ngroups << 3; e < n; e++)
            osc[e] = eval_elem(xsc[e], tsc[e], Tsc[e], r, alpha, r_la, c0, &sP[0][0]);
    }
}

extern "C" void kernel_launch(void* const* d_in, const int* in_sizes, int n_in,
                              void* d_out, int out_size) {
    const int*   x   = (const int*)d_in[0];
    const float* t_x = (const float*)d_in[1];
    const float* T   = (const float*)d_in[2];
    const float* lr  = (const float*)d_in[3];
    const float* lal = (const float*)d_in[4];
    const float* la  = (const float*)d_in[5];
    const float* lb  = (const float*)d_in[6];
    float* out = (float*)d_out;
    int n = in_sizes[0];

    setup_kernel<<<NX, 64>>>(lr, lal, la, lb);

    int threads = 256;
    int ngroups = n >> 3;
    // ~4 groups per thread
    int blocks = (ngroups + threads * 4 - 1) / (threads * 4);
    if (blocks < 1) blocks = 1;
    bgnbd_kernel<<<blocks, threads>>>((const int4*)x, (const float4*)t_x,
                                      (const float4*)T, (float4*)out, n);
}